// round 15
// baseline (speedup 1.0000x reference)
#include <cuda_runtime.h>
#include <cuda_bf16.h>
#include <cuda_fp16.h>
#include <cstdint>
#include <math.h>

// Problem constants
#define NE    65536      // edges
#define NL    3          // metapath length
#define NELT  196608     // NE*NL tokens
#define NN    20000      // nodes
#define NNP   20096      // nodes padded to multiple of 128 (157*128)
#define NT    16384      // targets
#define ND    128        // model dim
#define NFF   2048       // FF dim
#define NAH   4          // attention heads
#define NH    8          // output heads
#define FFC   512        // FFN hidden N-chunk width (NFF/4)

typedef __half h16;

// ---------------------------------------------------------------------------
// Static device scratch (~1.2 GB; must stay < 2 GB or host link fails with
// GOTPCREL relocation overflow — learned in R4)
// ---------------------------------------------------------------------------
__device__ h16   g_fh    [(size_t)NNP * ND];         // feature split planes (A)
__device__ h16   g_fl    [(size_t)NNP * ND];
__device__ float g_nqkv  [(size_t)NNP * 3 * ND];     // per-NODE qkv projection
__device__ h16   g_ah    [(size_t)NELT * ND];        // attention out planes
__device__ h16   g_al    [(size_t)NELT * ND];
__device__ h16   g_x1h   [(size_t)NELT * ND];        // post-LN1 split planes
__device__ h16   g_x1l   [(size_t)NELT * ND];
__device__ h16   g_hh    [(size_t)NELT * FFC];       // FFN hidden planes
__device__ h16   g_hl    [(size_t)NELT * FFC];
__device__ float g_ffo   [(size_t)NELT * ND];        // outproj out, then FFN out
__device__ h16   g_hidh  [(size_t)NE * ND];          // hidden (mean over L)
__device__ h16   g_hidl  [(size_t)NE * ND];
__device__ float g_eft   [(size_t)NE * NH * ND];     // rnn projection fp32
__device__ float g_a     [(size_t)NE * NH];
__device__ float g_expa  [(size_t)NE * NH];
__device__ unsigned g_menc[(size_t)NN * NH];
__device__ float g_s     [(size_t)NN * NH];
__device__ float g_ft    [(size_t)NN * NH * ND];
// weight planes (single fp16 plane each — W residual is the dropped term)
__device__ h16 g_iwf[3 * ND * ND];
__device__ h16 g_owf[ND * ND];
__device__ h16 g_w1f[NFF * ND];
__device__ h16 g_w2f[ND * NFF];
__device__ h16 g_rwf[NH * ND * ND];

// ---------------------------------------------------------------------------
// Helpers
// ---------------------------------------------------------------------------
__device__ __forceinline__ uint32_t smem_u32(const void* p) {
    uint32_t a;
    asm("{ .reg .u64 t; cvta.to.shared.u64 t, %1; cvt.u32.u64 %0, t; }" : "=r"(a) : "l"(p));
    return a;
}
__device__ __forceinline__ void ldsm4(uint32_t* r, uint32_t addr) {
    asm volatile("ldmatrix.sync.aligned.m8n8.x4.shared.b16 {%0,%1,%2,%3}, [%4];"
                 : "=r"(r[0]), "=r"(r[1]), "=r"(r[2]), "=r"(r[3]) : "r"(addr));
}
__device__ __forceinline__ void mma16816(float* c, const uint32_t* a,
                                         uint32_t b0, uint32_t b1) {
    asm volatile("mma.sync.aligned.m16n8k16.row.col.f32.f16.f16.f32 "
                 "{%0,%1,%2,%3}, {%4,%5,%6,%7}, {%8,%9}, {%0,%1,%2,%3};"
                 : "+f"(c[0]), "+f"(c[1]), "+f"(c[2]), "+f"(c[3])
                 : "r"(a[0]), "r"(a[1]), "r"(a[2]), "r"(a[3]), "r"(b0), "r"(b1));
}
__device__ __forceinline__ void cpa16(uint32_t saddr, const void* g) {
    asm volatile("cp.async.cg.shared.global [%0], [%1], 16;" :: "r"(saddr), "l"(g));
}
#define CPA_COMMIT() asm volatile("cp.async.commit_group;" ::: "memory")
#define CPA_WAIT0()  asm volatile("cp.async.wait_group 0;" ::: "memory")

__device__ __forceinline__ void splitf(float v, h16& h, h16& l) {
    h = __float2half(v);
    l = __float2half(v - __half2float(h));
}
__device__ __forceinline__ unsigned encf(float f) {
    unsigned u = __float_as_uint(f);
    return (u & 0x80000000u) ? ~u : (u | 0x80000000u);
}
__device__ __forceinline__ float decf(unsigned u) {
    return (u & 0x80000000u) ? __uint_as_float(u ^ 0x80000000u)
                             : __uint_as_float(~u);
}

// ---------------------------------------------------------------------------
// HMMA 2-pass split-fp16 GEMM, BK=64, 2-stage cp.async ring.
// C[M,N] = act((Ahi+Alo)[M,K](lda) @ Wf[N,K](ldw)^T + bias)
// 256 threads, 8 warps (4m x 2n, warp tile 32x64), CTA tile 128x128.
// K chunks of 64: 128 MMAs per barrier (R6 pipeline structure, half the
// barrier/wait overhead per MMA). Stage = 3 planes of 128x64 fp16 = 55KB,
// 2-stage ring = 110.6KB -> still 2 CTAs/SM (228KB/SM).
// Per kk: b fragments loaded ONCE, used by both A-passes.
// mode 0: Cf = acc + bias.  mode 1: relu(acc+bias) -> split fp16 planes.
// mode 2: Cf += acc (accumulate, no bias).
// All dims are exact multiples of tiles -> no bounds checks.
// ---------------------------------------------------------------------------
#define SP 72                                   // padded SMEM row stride (elems)
#define PLS  (128 * SP * 2)                     // plane stride bytes (18432)
#define STG3 (3 * PLS)                          // stage stride bytes (55296)
#define HG_SMEM (2 * STG3)                      // 110592 bytes dynamic SMEM

__global__ __launch_bounds__(256)
void hgemm(const h16* __restrict__ Ahi, const h16* __restrict__ Alo, int lda,
           const h16* __restrict__ Wf, int ldw,
           const float* __restrict__ bias,
           float* __restrict__ Cf, h16* __restrict__ Chi, h16* __restrict__ Clo,
           int ldc, int K, int mode) {
    extern __shared__ h16 smdyn[];
    const uint32_t sbase = smem_u32(smdyn);

    const int tid  = threadIdx.x;
    const int wid  = tid >> 5;
    const int lane = tid & 31;
    const int wm   = wid & 3;         // 4 m-groups * 32 rows
    const int wn   = wid >> 2;        // 2 n-groups * 64 cols
    const size_t bm = (size_t)blockIdx.x * 128;
    const size_t bn = (size_t)blockIdx.y * 128;

    // staging table: 3072 16B-units per chunk (3 planes x 128 rows x 8 q), 12/thread
    const h16* gp[12];
    uint32_t doff[12];
#pragma unroll
    for (int i = 0; i < 12; i++) {
        int u = tid + 256 * i;
        int plane = u >> 10;          // 0=Ah 1=Al 2=Wf
        int rem = u & 1023;
        int row = rem >> 3;
        int q = rem & 7;
        const h16* b;
        int ld;
        if (plane == 0)      { b = Ahi + bm * (size_t)lda; ld = lda; }
        else if (plane == 1) { b = Alo + bm * (size_t)lda; ld = lda; }
        else                 { b = Wf  + bn * (size_t)ldw; ld = ldw; }
        gp[i] = b + (size_t)row * ld + q * 8;
        doff[i] = plane * PLS + (row * SP + q * 8) * 2;
    }
#define ISSUE(k0, slot) do {                                                 \
        uint32_t sb_ = sbase + (slot) * STG3;                                \
        _Pragma("unroll")                                                    \
        for (int i = 0; i < 12; i++) cpa16(sb_ + doff[i], gp[i] + (k0));     \
    } while (0)

    // ldmatrix coords
    const int frow = lane & 15;
    const int fcol = (lane >> 4) << 3;

    float acc[2][8][4];
#pragma unroll
    for (int i = 0; i < 2; i++)
#pragma unroll
        for (int j = 0; j < 8; j++)
#pragma unroll
            for (int q = 0; q < 4; q++) acc[i][j][q] = 0.0f;

    const int nch = K >> 6;           // chunks of 64

    // prologue: chunk 0 into slot 0
    ISSUE(0, 0);
    CPA_COMMIT();

    for (int c = 0; c < nch; c++) {
        CPA_WAIT0();
        __syncthreads();
        if (c + 1 < nch) {
            ISSUE((c + 1) << 6, (c + 1) & 1);
            CPA_COMMIT();
        }
        const uint32_t cb = sbase + (c & 1) * STG3;
#pragma unroll
        for (int kk = 0; kk < 64; kk += 16) {
            uint32_t ah[2][4], al[2][4];
#pragma unroll
            for (int mf = 0; mf < 2; mf++) {
                uint32_t ra = ((wm * 32 + mf * 16 + frow) * SP + kk + fcol) * 2;
                ldsm4(ah[mf], cb + ra);
                ldsm4(al[mf], cb + PLS + ra);
            }
#pragma unroll
            for (int g = 0; g < 4; g++) {
                uint32_t b[4];
                ldsm4(b, cb + 2 * PLS +
                      ((wn * 64 + g * 16 + frow) * SP + kk + fcol) * 2);
#pragma unroll
                for (int mf = 0; mf < 2; mf++) {
                    mma16816(acc[mf][g * 2],     ah[mf], b[0], b[2]);
                    mma16816(acc[mf][g * 2 + 1], ah[mf], b[1], b[3]);
                    mma16816(acc[mf][g * 2],     al[mf], b[0], b[2]);
                    mma16816(acc[mf][g * 2 + 1], al[mf], b[1], b[3]);
                }
            }
        }
    }

    // Epilogue. D thread map: row = t/4 (+8 for regs 2,3), col = 2*(t%4)+{0,1}
    const int tr = lane >> 2;
    const int tc = (lane & 3) * 2;
    const size_t m0 = bm + wm * 32;
    const size_t n0 = bn + wn * 64;
#pragma unroll
    for (int mf = 0; mf < 2; mf++) {
#pragma unroll
        for (int hh = 0; hh < 2; hh++) {
            size_t row = m0 + mf * 16 + tr + hh * 8;
#pragma unroll
            for (int nf = 0; nf < 8; nf++) {
                size_t col = n0 + nf * 8 + tc;
                float a0 = acc[mf][nf][hh * 2];
                float a1 = acc[mf][nf][hh * 2 + 1];
                if (mode == 0) {
                    float2 o;
                    o.x = a0 + bias[col];
                    o.y = a1 + bias[col + 1];
                    *(float2*)&Cf[row * (size_t)ldc + col] = o;
                } else if (mode == 2) {
                    float2 old = *(float2*)&Cf[row * (size_t)ldc + col];
                    old.x += a0;
                    old.y += a1;
                    *(float2*)&Cf[row * (size_t)ldc + col] = old;
                } else {
                    float v0 = fmaxf(a0 + bias[col], 0.0f);
                    float v1 = fmaxf(a1 + bias[col + 1], 0.0f);
                    h16 h0, l0, h1, l1;
                    splitf(v0, h0, l0);
                    splitf(v1, h1, l1);
                    __half2 hp; hp.x = h0; hp.y = h1;
                    __half2 lp; lp.x = l0; lp.y = l1;
                    *(__half2*)&Chi[row * (size_t)ldc + col] = hp;
                    *(__half2*)&Clo[row * (size_t)ldc + col] = lp;
                }
            }
        }
    }
#undef ISSUE
}

// ---------------------------------------------------------------------------
// Fused weight-convert + feature-split (one launch)
// ---------------------------------------------------------------------------
#define WN0 (3 * ND * ND)
#define WN1 (WN0 + ND * ND)
#define WN2 (WN1 + NFF * ND)
#define WN3 (WN2 + ND * NFF)
#define WN4 (WN3 + NH * ND * ND)
#define WN5 (WN4 + NNP * ND)

__global__ void wsplit_all(const float* __restrict__ in_w,
                           const float* __restrict__ out_w,
                           const float* __restrict__ w1,
                           const float* __restrict__ w2,
                           const float* __restrict__ rnn_w,
                           const float* __restrict__ feat) {
    int i = blockIdx.x * 256 + threadIdx.x;
    if (i >= WN5) return;
    if (i >= WN4) {
        int j = i - WN4;              // padded feature planes (A operand: split)
        float v = (j < NN * ND) ? feat[j] : 0.0f;
        h16 hh, ll;
        splitf(v, hh, ll);
        g_fh[j] = hh;
        g_fl[j] = ll;
        return;
    }
    const float* s; h16* h; int j;
    if (i < WN0)      { s = in_w;  h = g_iwf; j = i; }
    else if (i < WN1) { s = out_w; h = g_owf; j = i - WN0; }
    else if (i < WN2) { s = w1;    h = g_w1f; j = i - WN1; }
    else if (i < WN3) { s = w2;    h = g_w2f; j = i - WN2; }
    else              { s = rnn_w; h = g_rwf; j = i - WN3; }
    h[j] = __float2half(s[j]);
}

// ---------------------------------------------------------------------------
// K0: zero per-launch accumulators
// ---------------------------------------------------------------------------
__global__ void zero_kernel() {
    int i = blockIdx.x * 256 + threadIdx.x;
    if (i < NN * NH * ND) g_ft[i] = 0.0f;
    if (i < NN * NH) { g_s[i] = 0.0f; g_menc[i] = 0u; }
}

// ---------------------------------------------------------------------------
// K3: tiny attention (L=3, AH=4, HD=32) — one warp per edge, vectorized:
// lane owns 4 consecutive dims (float4); head = lane>>3; dot products reduce
// over the 8-lane group (3-step butterfly). Node qkv table is L2-resident.
// ---------------------------------------------------------------------------
__global__ __launch_bounds__(256)
void attn_kernel(const int* __restrict__ emi) {
    int warp = (blockIdx.x * blockDim.x + threadIdx.x) >> 5;
    int lane = threadIdx.x & 31;

    float4 q[NL], k[NL], v[NL];
#pragma unroll
    for (int l = 0; l < NL; l++) {
        int node = emi[warp * NL + l];
        const float* base = g_nqkv + (size_t)node * 384 + lane * 4;
        q[l] = *(const float4*)(base);
        k[l] = *(const float4*)(base + 128);
        v[l] = *(const float4*)(base + 256);
    }

    const float scale = 0.1767766952966369f; // 1/sqrt(32)
    // scores s[l][m]: reduce q[l]·k[m] over the 8-lane head group
    float s[NL][NL];
#pragma unroll
    for (int l = 0; l < NL; l++)
#pragma unroll
        for (int m = 0; m < NL; m++) {
            float p = q[l].x * k[m].x + q[l].y * k[m].y
                    + q[l].z * k[m].z + q[l].w * k[m].w;
            p += __shfl_xor_sync(0xFFFFFFFFu, p, 1);
            p += __shfl_xor_sync(0xFFFFFFFFu, p, 2);
            p += __shfl_xor_sync(0xFFFFFFFFu, p, 4);
            s[l][m] = p * scale;
        }

#pragma unroll
    for (int l = 0; l < NL; l++) {
        float mx = fmaxf(s[l][0], fmaxf(s[l][1], s[l][2]));
        float e0 = expf(s[l][0] - mx);
        float e1 = expf(s[l][1] - mx);
        float e2 = expf(s[l][2] - mx);
        float inv = 1.0f / (e0 + e1 + e2);
        float o0 = (e0 * v[0].x + e1 * v[1].x + e2 * v[2].x) * inv;
        float o1 = (e0 * v[0].y + e1 * v[1].y + e2 * v[2].y) * inv;
        float o2 = (e0 * v[0].z + e1 * v[1].z + e2 * v[2].z) * inv;
        float o3 = (e0 * v[0].w + e1 * v[1].w + e2 * v[2].w) * inv;
        size_t idx = ((size_t)warp * NL + l) * ND + lane * 4;
        h16 h0, l0, h1, l1, h2, l2, h3, l3;
        splitf(o0, h0, l0); splitf(o1, h1, l1);
        splitf(o2, h2, l2); splitf(o3, h3, l3);
        __half2 hp0, hp1, lp0, lp1;
        hp0.x = h0; hp0.y = h1; hp1.x = h2; hp1.y = h3;
        lp0.x = l0; lp0.y = l1; lp1.x = l2; lp1.y = l3;
        uint2 hv, lv;
        hv.x = *(uint32_t*)&hp0; hv.y = *(uint32_t*)&hp1;
        lv.x = *(uint32_t*)&lp0; lv.y = *(uint32_t*)&lp1;
        *(uint2*)&g_ah[idx] = hv;
        *(uint2*)&g_al[idx] = lv;
    }
}

// ---------------------------------------------------------------------------
// K5: x1 = LN1(features[emi] + oproj); writes split planes only
// ---------------------------------------------------------------------------
__global__ __launch_bounds__(256)
void addln_kernel(const float* __restrict__ feat, const int* __restrict__ emi,
                  const float* __restrict__ gam, const float* __restrict__ bet) {
    int warp = (blockIdx.x * blockDim.x + threadIdx.x) >> 5;   // token index
    int lane = threadIdx.x & 31;
    int node = emi[warp];
    const float* xr = feat + (size_t)node * ND;
    const float* yr = g_ffo + (size_t)warp * ND;
    float v[4], s = 0.0f;
#pragma unroll
    for (int i = 0; i < 4; i++) {
        v[i] = xr[i * 32 + lane] + yr[i * 32 + lane];
        s += v[i];
    }
#pragma unroll
    for (int off = 16; off; off >>= 1) s += __shfl_xor_sync(0xFFFFFFFFu, s, off);
    float mu = s * (1.0f / 128.0f);
    float vs = 0.0f;
#pragma unroll
    for (int i = 0; i < 4; i++) { float d = v[i] - mu; vs += d * d; }
#pragma unroll
    for (int off = 16; off; off >>= 1) vs += __shfl_xor_sync(0xFFFFFFFFu, vs, off);
    float inv = rsqrtf(vs * (1.0f / 128.0f) + 1e-5f);
#pragma unroll
    for (int i = 0; i < 4; i++) {
        size_t idx = (size_t)warp * ND + i * 32 + lane;
        float r = (v[i] - mu) * inv * gam[i * 32 + lane] + bet[i * 32 + lane];
        h16 h, l;
        splitf(r, h, l);
        g_x1h[idx] = h;
        g_x1l[idx] = l;
    }
}

// ---------------------------------------------------------------------------
// K7: LN2 + mean over L -> hidden planes (x1 reconstructed from planes)
// ---------------------------------------------------------------------------
__global__ __launch_bounds__(256)
void ln2hidden_kernel(const float* __restrict__ gam, const float* __restrict__ bet) {
    int warp = (blockIdx.x * blockDim.x + threadIdx.x) >> 5;
    int lane = threadIdx.x & 31;
    float hid[4] = {0, 0, 0, 0};
#pragma unroll
    for (int l = 0; l < NL; l++) {
        size_t r = (size_t)warp * NL + l;
        const float* yr = g_ffo + r * ND;
        float v[4], s = 0.0f;
#pragma unroll
        for (int i = 0; i < 4; i++) {
            size_t idx = r * ND + i * 32 + lane;
            float x1 = __half2float(g_x1h[idx]) + __half2float(g_x1l[idx]);
            v[i] = x1 + yr[i * 32 + lane];
            s += v[i];
        }
#pragma unroll
        for (int off = 16; off; off >>= 1) s += __shfl_xor_sync(0xFFFFFFFFu, s, off);
        float mu = s * (1.0f / 128.0f);
        float vs = 0.0f;
#pragma unroll
        for (int i = 0; i < 4; i++) { float d = v[i] - mu; vs += d * d; }
#pragma unroll
        for (int off = 16; off; off >>= 1) vs += __shfl_xor_sync(0xFFFFFFFFu, vs, off);
        float inv = rsqrtf(vs * (1.0f / 128.0f) + 1e-5f);
#pragma unroll
        for (int i = 0; i < 4; i++)
            hid[i] += ((v[i] - mu) * inv * gam[i * 32 + lane] + bet[i * 32 + lane])
                      * (1.0f / 3.0f);
    }
#pragma unroll
    for (int i = 0; i < 4; i++) {
        size_t idx = (size_t)warp * ND + i * 32 + lane;
        h16 h, l;
        splitf(hid[i], h, l);
        g_hidh[idx] = h;
        g_hidl[idx] = l;
    }
}

// ---------------------------------------------------------------------------
// K9: per-edge logits + leaky relu + segment atomicMax
// ---------------------------------------------------------------------------
__global__ __launch_bounds__(256)
void amax_kernel(const float* __restrict__ feat, const int* __restrict__ emi,
                 const int* __restrict__ dst, const float* __restrict__ a1w,
                 const float* __restrict__ a2) {
    int warp = (blockIdx.x * blockDim.x + threadIdx.x) >> 5;
    int lane = threadIdx.x & 31;
    int node = emi[warp * NL + (NL - 1)];
    int d = dst[warp];
    float c[4];
#pragma unroll
    for (int i = 0; i < 4; i++) c[i] = feat[(size_t)node * ND + i * 32 + lane];
#pragma unroll
    for (int h = 0; h < NH; h++) {
        const float* w   = a1w + h * ND;
        const float* efr = g_eft + (size_t)warp * (NH * ND) + h * ND;
        const float* at2 = a2 + h * ND;
        float p = 0.0f;
#pragma unroll
        for (int i = 0; i < 4; i++)
            p += c[i] * w[i * 32 + lane] + efr[i * 32 + lane] * at2[i * 32 + lane];
#pragma unroll
        for (int off = 16; off; off >>= 1) p += __shfl_xor_sync(0xFFFFFFFFu, p, off);
        if (lane == 0) {
            float av = p > 0.0f ? p : 0.01f * p;
            g_a[warp * NH + h] = av;
            atomicMax(&g_menc[d * NH + h], encf(av));
        }
    }
}

// ---------------------------------------------------------------------------
// K10: e = exp(a - m[dst]); segment sum
// ---------------------------------------------------------------------------
__global__ void exps_kernel(const int* __restrict__ dst) {
    int i = blockIdx.x * 256 + threadIdx.x;
    int e = i >> 3, h = i & 7;
    int d = dst[e];
    float m = decf(g_menc[d * NH + h]);
    float ex = expf(g_a[i] - m);
    g_expa[i] = ex;
    atomicAdd(&g_s[d * NH + h], ex);
}

// ---------------------------------------------------------------------------
// K11: ft[dst] += eft * (e / s[dst])
// ---------------------------------------------------------------------------
__global__ void ftacc_kernel(const int* __restrict__ dst) {
    size_t i = (size_t)blockIdx.x * 256 + threadIdx.x;
    int e = (int)(i >> 10);
    int j = (int)(i & 1023);
    int h = j >> 7;
    int d = dst[e];
    float w = g_expa[e * NH + h] / g_s[d * NH + h];
    atomicAdd(&g_ft[(size_t)d * (NH * ND) + j], g_eft[i] * w);
}

// ---------------------------------------------------------------------------
// K12: out = ft[target_idx]
// ---------------------------------------------------------------------------
__global__ void outg_kernel(const int* __restrict__ tgt, float* __restrict__ out) {
    size_t i = (size_t)blockIdx.x * 256 + threadIdx.x;
    int t = (int)(i >> 10);
    int j = (int)(i & 1023);
    out[i] = g_ft[(size_t)tgt[t] * (NH * ND) + j];
}

// ---------------------------------------------------------------------------
extern "C" void kernel_launch(void* const* d_in, const int* in_sizes, int n_in,
                              void* d_out, int out_size) {
    const float* features = (const float*)d_in[0];
    const int*   emi      = (const int*)d_in[1];
    const int*   dst      = (const int*)d_in[2];
    const int*   tgt      = (const int*)d_in[3];
    const float* in_w     = (const float*)d_in[4];
    const float* in_b     = (const float*)d_in[5];
    const float* out_w    = (const float*)d_in[6];
    const float* out_b    = (const float*)d_in[7];
    const float* ln1_g    = (const float*)d_in[8];
    const float* ln1_b    = (const float*)d_in[9];
    const float* w1       = (const float*)d_in[10];
    const float* b1       = (const float*)d_in[11];
    const float* w2       = (const float*)d_in[12];
    const float* b2       = (const float*)d_in[13];
    const float* ln2_g    = (const float*)d_in[14];
    const float* ln2_b    = (const float*)d_in[15];
    const float* rnn_w    = (const float*)d_in[16];
    const float* rnn_b    = (const float*)d_in[17];
    const float* a1w      = (const float*)d_in[18];
    const float* a2       = (const float*)d_in[19];
    float* out = (float*)d_out;

    cudaFuncSetAttribute(hgemm, cudaFuncAttributeMaxDynamicSharedMemorySize, HG_SMEM);

    // Resolve device-global addresses (query-only; capture safe)
    float *pnqkv, *pffo, *peft;
    h16 *pfh, *pfl, *pah, *pal, *px1h, *px1l, *phh, *phl, *phidh, *phidl;
    h16 *piwf, *powf, *pw1f, *pw2f, *prwf;
    cudaGetSymbolAddress((void**)&pnqkv, g_nqkv);
    cudaGetSymbolAddress((void**)&pffo,  g_ffo);
    cudaGetSymbolAddress((void**)&peft,  g_eft);
    cudaGetSymbolAddress((void**)&pfh,   g_fh);
    cudaGetSymbolAddress((void**)&pfl,   g_fl);
    cudaGetSymbolAddress((void**)&pah,   g_ah);
    cudaGetSymbolAddress((void**)&pal,   g_al);
    cudaGetSymbolAddress((void**)&px1h,  g_x1h);
    cudaGetSymbolAddress((void**)&px1l,  g_x1l);
    cudaGetSymbolAddress((void**)&phh,   g_hh);
    cudaGetSymbolAddress((void**)&phl,   g_hl);
    cudaGetSymbolAddress((void**)&phidh, g_hidh);
    cudaGetSymbolAddress((void**)&phidl, g_hidl);
    cudaGetSymbolAddress((void**)&piwf,  g_iwf);
    cudaGetSymbolAddress((void**)&powf,  g_owf);
    cudaGetSymbolAddress((void**)&pw1f,  g_w1f);
    cudaGetSymbolAddress((void**)&pw2f,  g_w2f);
    cudaGetSymbolAddress((void**)&prwf,  g_rwf);

    // L0: convert weights to fp16 + split padded feature planes (one launch)
    wsplit_all<<<(WN5 + 255) / 256, 256>>>(in_w, out_w, w1, w2, rnn_w, features);

    // L1: zero accumulators
    zero_kernel<<<(NN * NH * ND + 255) / 256, 256>>>();

    // L2: node-level QKV = features @ in_w^T + in_b : [20096,128]x[384,128]
    hgemm<<<dim3(NNP / 128, 3), 256, HG_SMEM>>>(
        pfh, pfl, ND, piwf, ND, in_b, pnqkv, nullptr, nullptr, 384, ND, 0);

    // L3: attention (gathers node qkv via emi; node table is L2-resident)
    attn_kernel<<<NE / 8, 256>>>(emi);

    // L4: out projection -> g_ffo fp32
    hgemm<<<dim3(NELT / 128, 1), 256, HG_SMEM>>>(
        pah, pal, ND, powf, ND, out_b, pffo, nullptr, nullptr, ND, ND, 0);

    // L5: x1 = LN1(features[emi] + oproj)
    addln_kernel<<<NELT / 8, 256>>>(features, emi, ln1_g, ln1_b);

    // L6: FFN in 4 hidden N-chunks of FFC=512; FFN2 accumulates into g_ffo
    for (int c = 0; c < NFF / FFC; c++) {
        hgemm<<<dim3(NELT / 128, FFC / 128), 256, HG_SMEM>>>(
            px1h, px1l, ND,
            pw1f + (size_t)c * FFC * ND, ND,
            b1 + c * FFC, nullptr, phh, phl, FFC, ND, 1);
        hgemm<<<dim3(NELT / 128, 1), 256, HG_SMEM>>>(
            phh, phl, FFC,
            pw2f + (size_t)c * FFC, NFF,
            b2, pffo, nullptr, nullptr, ND, FFC, c == 0 ? 0 : 2);
    }

    // L7: x2 = LN2(x1 + ff); hidden = mean_L(x2) -> planes
    ln2hidden_kernel<<<NE / 8, 256>>>(ln2_g, ln2_b);

    // L8: eft = hidden @ rnn_w^T + rnn_b : [65536,128]x[1024,128]
    hgemm<<<dim3(NE / 128, (NH * ND) / 128), 256, HG_SMEM>>>(
        phidh, phidl, ND, prwf, ND, rnn_b, peft, nullptr, nullptr,
        NH * ND, ND, 0);

    // L9-12: segment softmax aggregation + output gather
    amax_kernel<<<NE / 8, 256>>>(features, emi, dst, a1w, a2);
    exps_kernel<<<NE * NH / 256, 256>>>(dst);
    ftacc_kernel<<<(int)((size_t)NE * NH * ND / 256), 256>>>(dst);
    outg_kernel<<<(int)((size_t)NT * NH * ND / 256), 256>>>(tgt, out);
}

// round 16
// speedup vs baseline: 1.1749x; 1.1749x over previous
#include <cuda_runtime.h>
#include <cuda_bf16.h>
#include <cuda_fp16.h>
#include <cstdint>
#include <math.h>

// Problem constants
#define NE    65536      // edges
#define NL    3          // metapath length
#define NELT  196608     // NE*NL tokens
#define NN    20000      // nodes
#define NNP   20096      // nodes padded to multiple of 128 (157*128)
#define NT    16384      // targets
#define ND    128        // model dim
#define NFF   2048       // FF dim
#define NAH   4          // attention heads
#define NH    8          // output heads
#define FFC   512        // FFN hidden N-chunk width (NFF/4)

typedef __half h16;

// ---------------------------------------------------------------------------
// Static device scratch (~1.2 GB; must stay < 2 GB or host link fails with
// GOTPCREL relocation overflow — learned in R4)
// ---------------------------------------------------------------------------
__device__ h16   g_fh    [(size_t)NNP * ND];         // feature split planes (A)
__device__ h16   g_fl    [(size_t)NNP * ND];
__device__ float g_nqkv  [(size_t)NNP * 3 * ND];     // per-NODE qkv projection
__device__ h16   g_ah    [(size_t)NELT * ND];        // attention out planes
__device__ h16   g_al    [(size_t)NELT * ND];
__device__ h16   g_x1h   [(size_t)NELT * ND];        // post-LN1 split planes
__device__ h16   g_x1l   [(size_t)NELT * ND];
__device__ h16   g_hh    [(size_t)NELT * FFC];       // FFN hidden planes
__device__ h16   g_hl    [(size_t)NELT * FFC];
__device__ float g_ffo   [(size_t)NELT * ND];        // outproj out, then FFN out
__device__ h16   g_hidh  [(size_t)NE * ND];          // hidden (mean over L)
__device__ h16   g_hidl  [(size_t)NE * ND];
__device__ float g_eft   [(size_t)NE * NH * ND];     // rnn projection fp32
__device__ float g_a     [(size_t)NE * NH];
__device__ float g_expa  [(size_t)NE * NH];
__device__ unsigned g_menc[(size_t)NN * NH];
__device__ float g_s     [(size_t)NN * NH];
__device__ float g_ft    [(size_t)NN * NH * ND];
// weight planes (single fp16 plane each — W residual is the dropped term)
__device__ h16 g_iwf[3 * ND * ND];
__device__ h16 g_owf[ND * ND];
__device__ h16 g_w1f[NFF * ND];
__device__ h16 g_w2f[ND * NFF];
__device__ h16 g_rwf[NH * ND * ND];

// ---------------------------------------------------------------------------
// Helpers
// ---------------------------------------------------------------------------
__device__ __forceinline__ uint32_t smem_u32(const void* p) {
    uint32_t a;
    asm("{ .reg .u64 t; cvta.to.shared.u64 t, %1; cvt.u32.u64 %0, t; }" : "=r"(a) : "l"(p));
    return a;
}
__device__ __forceinline__ void ldsm4(uint32_t* r, uint32_t addr) {
    asm volatile("ldmatrix.sync.aligned.m8n8.x4.shared.b16 {%0,%1,%2,%3}, [%4];"
                 : "=r"(r[0]), "=r"(r[1]), "=r"(r[2]), "=r"(r[3]) : "r"(addr));
}
__device__ __forceinline__ void mma16816(float* c, const uint32_t* a,
                                         uint32_t b0, uint32_t b1) {
    asm volatile("mma.sync.aligned.m16n8k16.row.col.f32.f16.f16.f32 "
                 "{%0,%1,%2,%3}, {%4,%5,%6,%7}, {%8,%9}, {%0,%1,%2,%3};"
                 : "+f"(c[0]), "+f"(c[1]), "+f"(c[2]), "+f"(c[3])
                 : "r"(a[0]), "r"(a[1]), "r"(a[2]), "r"(a[3]), "r"(b0), "r"(b1));
}
__device__ __forceinline__ void cpa16(uint32_t saddr, const void* g) {
    asm volatile("cp.async.cg.shared.global [%0], [%1], 16;" :: "r"(saddr), "l"(g));
}
#define CPA_COMMIT() asm volatile("cp.async.commit_group;" ::: "memory")
#define CPA_WAIT1()  asm volatile("cp.async.wait_group 1;" ::: "memory")

__device__ __forceinline__ void splitf(float v, h16& h, h16& l) {
    h = __float2half(v);
    l = __float2half(v - __half2float(h));
}
__device__ __forceinline__ unsigned encf(float f) {
    unsigned u = __float_as_uint(f);
    return (u & 0x80000000u) ? ~u : (u | 0x80000000u);
}
__device__ __forceinline__ float decf(unsigned u) {
    return (u & 0x80000000u) ? __uint_as_float(u ^ 0x80000000u)
                             : __uint_as_float(~u);
}

// ---------------------------------------------------------------------------
// HMMA 2-pass split-fp16 GEMM, 3-stage cp.async ring — the R11 configuration
// that measured 2720us total (BK=64 in R15 regressed; this is the optimum).
// C[M,N] = act((Ahi+Alo)[M,K](lda) @ Wf[N,K](ldw)^T + bias)
// 256 threads, 8 warps (4m x 2n, warp tile 32x64), CTA tile 128x128,
// K chunks of 32. Stage = 3 planes {Ah, Al, Wf} of 128x32 fp16 = 30KB.
// Per kk: b fragments loaded ONCE, used by both A-passes.
// Ring slots tracked with incremental put/get counters.
// mode 0: Cf = acc + bias.  mode 1: relu(acc+bias) -> split fp16 planes.
// mode 2: Cf += acc (accumulate, no bias).
// All dims are exact multiples of tiles -> no bounds checks.
// ---------------------------------------------------------------------------
#define SP 40                                   // padded SMEM row stride (elems)
#define PLS  (128 * SP * 2)                     // plane stride bytes (10240)
#define STG3 (3 * PLS)                          // stage stride bytes (30720)
#define NSTG 3                                  // ring depth
#define HG_SMEM (NSTG * STG3)                   // 92160 bytes dynamic SMEM

__global__ __launch_bounds__(256)
void hgemm(const h16* __restrict__ Ahi, const h16* __restrict__ Alo, int lda,
           const h16* __restrict__ Wf, int ldw,
           const float* __restrict__ bias,
           float* __restrict__ Cf, h16* __restrict__ Chi, h16* __restrict__ Clo,
           int ldc, int K, int mode) {
    extern __shared__ h16 smdyn[];
    const uint32_t sbase = smem_u32(smdyn);

    const int tid  = threadIdx.x;
    const int wid  = tid >> 5;
    const int lane = tid & 31;
    const int wm   = wid & 3;         // 4 m-groups * 32 rows
    const int wn   = wid >> 2;        // 2 n-groups * 64 cols
    const size_t bm = (size_t)blockIdx.x * 128;
    const size_t bn = (size_t)blockIdx.y * 128;

    // staging table: 1536 16B-units per chunk, 6 per thread
    const h16* gp[6];
    uint32_t doff[6];
#pragma unroll
    for (int i = 0; i < 6; i++) {
        int u = tid + 256 * i;
        int plane = u >> 9;           // 0=Ah 1=Al 2=Wf
        int rem = u & 511;
        int row = rem >> 2;
        int q = rem & 3;
        const h16* b;
        int ld;
        if (plane == 0)      { b = Ahi + bm * (size_t)lda; ld = lda; }
        else if (plane == 1) { b = Alo + bm * (size_t)lda; ld = lda; }
        else                 { b = Wf  + bn * (size_t)ldw; ld = ldw; }
        gp[i] = b + (size_t)row * ld + q * 8;
        doff[i] = plane * PLS + (row * SP + q * 8) * 2;
    }
#define ISSUE(k0, slot) do {                                                 \
        uint32_t sb_ = sbase + (slot) * STG3;                                \
        _Pragma("unroll")                                                    \
        for (int i = 0; i < 6; i++) cpa16(sb_ + doff[i], gp[i] + (k0));      \
    } while (0)

    // ldmatrix coords
    const int frow = lane & 15;
    const int fcol = (lane >> 4) << 3;

    float acc[2][8][4];
#pragma unroll
    for (int i = 0; i < 2; i++)
#pragma unroll
        for (int j = 0; j < 8; j++)
#pragma unroll
            for (int q = 0; q < 4; q++) acc[i][j][q] = 0.0f;

    const int nch = K >> 5;

    // prologue: chunks 0 and 1 into slots 0, 1
    ISSUE(0, 0);  CPA_COMMIT();
    ISSUE(32, 1); CPA_COMMIT();

    int put = 2;                      // next ring slot the loader writes
    int get = 0;                      // ring slot the consumer reads
    for (int c = 0; c < nch; c++) {
        CPA_WAIT1();                  // chunk c's group retired (FIFO)
        __syncthreads();
        if (c + 2 < nch) {
            ISSUE((c + 2) << 5, put);
            if (++put == NSTG) put = 0;
        }
        CPA_COMMIT();                 // empty-commit keeps the FIFO geometry
        const uint32_t cb = sbase + get * STG3;
        if (++get == NSTG) get = 0;
#pragma unroll
        for (int kk = 0; kk < 32; kk += 16) {
            uint32_t ah[2][4], al[2][4];
#pragma unroll
            for (int mf = 0; mf < 2; mf++) {
                uint32_t ra = ((wm * 32 + mf * 16 + frow) * SP + kk + fcol) * 2;
                ldsm4(ah[mf], cb + ra);
                ldsm4(al[mf], cb + PLS + ra);
            }
#pragma unroll
            for (int g = 0; g < 4; g++) {
                uint32_t b[4];
                ldsm4(b, cb + 2 * PLS +
                      ((wn * 64 + g * 16 + frow) * SP + kk + fcol) * 2);
#pragma unroll
                for (int mf = 0; mf < 2; mf++) {
                    mma16816(acc[mf][g * 2],     ah[mf], b[0], b[2]);
                    mma16816(acc[mf][g * 2 + 1], ah[mf], b[1], b[3]);
                    mma16816(acc[mf][g * 2],     al[mf], b[0], b[2]);
                    mma16816(acc[mf][g * 2 + 1], al[mf], b[1], b[3]);
                }
            }
        }
    }

    // Epilogue. D thread map: row = t/4 (+8 for regs 2,3), col = 2*(t%4)+{0,1}
    const int tr = lane >> 2;
    const int tc = (lane & 3) * 2;
    const size_t m0 = bm + wm * 32;
    const size_t n0 = bn + wn * 64;
#pragma unroll
    for (int mf = 0; mf < 2; mf++) {
#pragma unroll
        for (int hh = 0; hh < 2; hh++) {
            size_t row = m0 + mf * 16 + tr + hh * 8;
#pragma unroll
            for (int nf = 0; nf < 8; nf++) {
                size_t col = n0 + nf * 8 + tc;
                float a0 = acc[mf][nf][hh * 2];
                float a1 = acc[mf][nf][hh * 2 + 1];
                if (mode == 0) {
                    float2 o;
                    o.x = a0 + bias[col];
                    o.y = a1 + bias[col + 1];
                    *(float2*)&Cf[row * (size_t)ldc + col] = o;
                } else if (mode == 2) {
                    float2 old = *(float2*)&Cf[row * (size_t)ldc + col];
                    old.x += a0;
                    old.y += a1;
                    *(float2*)&Cf[row * (size_t)ldc + col] = old;
                } else {
                    float v0 = fmaxf(a0 + bias[col], 0.0f);
                    float v1 = fmaxf(a1 + bias[col + 1], 0.0f);
                    h16 h0, l0, h1, l1;
                    splitf(v0, h0, l0);
                    splitf(v1, h1, l1);
                    __half2 hp; hp.x = h0; hp.y = h1;
                    __half2 lp; lp.x = l0; lp.y = l1;
                    *(__half2*)&Chi[row * (size_t)ldc + col] = hp;
                    *(__half2*)&Clo[row * (size_t)ldc + col] = lp;
                }
            }
        }
    }
#undef ISSUE
}

// ---------------------------------------------------------------------------
// Fused weight-convert + feature-split (one launch)
// ---------------------------------------------------------------------------
#define WN0 (3 * ND * ND)
#define WN1 (WN0 + ND * ND)
#define WN2 (WN1 + NFF * ND)
#define WN3 (WN2 + ND * NFF)
#define WN4 (WN3 + NH * ND * ND)
#define WN5 (WN4 + NNP * ND)

__global__ void wsplit_all(const float* __restrict__ in_w,
                           const float* __restrict__ out_w,
                           const float* __restrict__ w1,
                           const float* __restrict__ w2,
                           const float* __restrict__ rnn_w,
                           const float* __restrict__ feat) {
    int i = blockIdx.x * 256 + threadIdx.x;
    if (i >= WN5) return;
    if (i >= WN4) {
        int j = i - WN4;              // padded feature planes (A operand: split)
        float v = (j < NN * ND) ? feat[j] : 0.0f;
        h16 hh, ll;
        splitf(v, hh, ll);
        g_fh[j] = hh;
        g_fl[j] = ll;
        return;
    }
    const float* s; h16* h; int j;
    if (i < WN0)      { s = in_w;  h = g_iwf; j = i; }
    else if (i < WN1) { s = out_w; h = g_owf; j = i - WN0; }
    else if (i < WN2) { s = w1;    h = g_w1f; j = i - WN1; }
    else if (i < WN3) { s = w2;    h = g_w2f; j = i - WN2; }
    else              { s = rnn_w; h = g_rwf; j = i - WN3; }
    h[j] = __float2half(s[j]);
}

// ---------------------------------------------------------------------------
// K0: zero per-launch accumulators
// ---------------------------------------------------------------------------
__global__ void zero_kernel() {
    int i = blockIdx.x * 256 + threadIdx.x;
    if (i < NN * NH * ND) g_ft[i] = 0.0f;
    if (i < NN * NH) { g_s[i] = 0.0f; g_menc[i] = 0u; }
}

// ---------------------------------------------------------------------------
// K3: tiny attention (L=3, AH=4, HD=32) — one warp per edge, vectorized:
// lane owns 4 consecutive dims (float4); head = lane>>3; dot products reduce
// over the 8-lane group (3-step butterfly). Node qkv table is L2-resident.
// (Measured 36us in R15 vs 91us scalar.)
// ---------------------------------------------------------------------------
__global__ __launch_bounds__(256)
void attn_kernel(const int* __restrict__ emi) {
    int warp = (blockIdx.x * blockDim.x + threadIdx.x) >> 5;
    int lane = threadIdx.x & 31;

    float4 q[NL], k[NL], v[NL];
#pragma unroll
    for (int l = 0; l < NL; l++) {
        int node = emi[warp * NL + l];
        const float* base = g_nqkv + (size_t)node * 384 + lane * 4;
        q[l] = *(const float4*)(base);
        k[l] = *(const float4*)(base + 128);
        v[l] = *(const float4*)(base + 256);
    }

    const float scale = 0.1767766952966369f; // 1/sqrt(32)
    float s[NL][NL];
#pragma unroll
    for (int l = 0; l < NL; l++)
#pragma unroll
        for (int m = 0; m < NL; m++) {
            float p = q[l].x * k[m].x + q[l].y * k[m].y
                    + q[l].z * k[m].z + q[l].w * k[m].w;
            p += __shfl_xor_sync(0xFFFFFFFFu, p, 1);
            p += __shfl_xor_sync(0xFFFFFFFFu, p, 2);
            p += __shfl_xor_sync(0xFFFFFFFFu, p, 4);
            s[l][m] = p * scale;
        }

#pragma unroll
    for (int l = 0; l < NL; l++) {
        float mx = fmaxf(s[l][0], fmaxf(s[l][1], s[l][2]));
        float e0 = expf(s[l][0] - mx);
        float e1 = expf(s[l][1] - mx);
        float e2 = expf(s[l][2] - mx);
        float inv = 1.0f / (e0 + e1 + e2);
        float o0 = (e0 * v[0].x + e1 * v[1].x + e2 * v[2].x) * inv;
        float o1 = (e0 * v[0].y + e1 * v[1].y + e2 * v[2].y) * inv;
        float o2 = (e0 * v[0].z + e1 * v[1].z + e2 * v[2].z) * inv;
        float o3 = (e0 * v[0].w + e1 * v[1].w + e2 * v[2].w) * inv;
        size_t idx = ((size_t)warp * NL + l) * ND + lane * 4;
        h16 h0, l0, h1, l1, h2, l2, h3, l3;
        splitf(o0, h0, l0); splitf(o1, h1, l1);
        splitf(o2, h2, l2); splitf(o3, h3, l3);
        __half2 hp0, hp1, lp0, lp1;
        hp0.x = h0; hp0.y = h1; hp1.x = h2; hp1.y = h3;
        lp0.x = l0; lp0.y = l1; lp1.x = l2; lp1.y = l3;
        uint2 hv, lv;
        hv.x = *(uint32_t*)&hp0; hv.y = *(uint32_t*)&hp1;
        lv.x = *(uint32_t*)&lp0; lv.y = *(uint32_t*)&lp1;
        *(uint2*)&g_ah[idx] = hv;
        *(uint2*)&g_al[idx] = lv;
    }
}

// ---------------------------------------------------------------------------
// K5: x1 = LN1(features[emi] + oproj); writes split planes only
// ---------------------------------------------------------------------------
__global__ __launch_bounds__(256)
void addln_kernel(const float* __restrict__ feat, const int* __restrict__ emi,
                  const float* __restrict__ gam, const float* __restrict__ bet) {
    int warp = (blockIdx.x * blockDim.x + threadIdx.x) >> 5;   // token index
    int lane = threadIdx.x & 31;
    int node = emi[warp];
    const float* xr = feat + (size_t)node * ND;
    const float* yr = g_ffo + (size_t)warp * ND;
    float v[4], s = 0.0f;
#pragma unroll
    for (int i = 0; i < 4; i++) {
        v[i] = xr[i * 32 + lane] + yr[i * 32 + lane];
        s += v[i];
    }
#pragma unroll
    for (int off = 16; off; off >>= 1) s += __shfl_xor_sync(0xFFFFFFFFu, s, off);
    float mu = s * (1.0f / 128.0f);
    float vs = 0.0f;
#pragma unroll
    for (int i = 0; i < 4; i++) { float d = v[i] - mu; vs += d * d; }
#pragma unroll
    for (int off = 16; off; off >>= 1) vs += __shfl_xor_sync(0xFFFFFFFFu, vs, off);
    float inv = rsqrtf(vs * (1.0f / 128.0f) + 1e-5f);
#pragma unroll
    for (int i = 0; i < 4; i++) {
        size_t idx = (size_t)warp * ND + i * 32 + lane;
        float r = (v[i] - mu) * inv * gam[i * 32 + lane] + bet[i * 32 + lane];
        h16 h, l;
        splitf(r, h, l);
        g_x1h[idx] = h;
        g_x1l[idx] = l;
    }
}

// ---------------------------------------------------------------------------
// K7: LN2 + mean over L -> hidden planes (x1 reconstructed from planes)
// ---------------------------------------------------------------------------
__global__ __launch_bounds__(256)
void ln2hidden_kernel(const float* __restrict__ gam, const float* __restrict__ bet) {
    int warp = (blockIdx.x * blockDim.x + threadIdx.x) >> 5;
    int lane = threadIdx.x & 31;
    float hid[4] = {0, 0, 0, 0};
#pragma unroll
    for (int l = 0; l < NL; l++) {
        size_t r = (size_t)warp * NL + l;
        const float* yr = g_ffo + r * ND;
        float v[4], s = 0.0f;
#pragma unroll
        for (int i = 0; i < 4; i++) {
            size_t idx = r * ND + i * 32 + lane;
            float x1 = __half2float(g_x1h[idx]) + __half2float(g_x1l[idx]);
            v[i] = x1 + yr[i * 32 + lane];
            s += v[i];
        }
#pragma unroll
        for (int off = 16; off; off >>= 1) s += __shfl_xor_sync(0xFFFFFFFFu, s, off);
        float mu = s * (1.0f / 128.0f);
        float vs = 0.0f;
#pragma unroll
        for (int i = 0; i < 4; i++) { float d = v[i] - mu; vs += d * d; }
#pragma unroll
        for (int off = 16; off; off >>= 1) vs += __shfl_xor_sync(0xFFFFFFFFu, vs, off);
        float inv = rsqrtf(vs * (1.0f / 128.0f) + 1e-5f);
#pragma unroll
        for (int i = 0; i < 4; i++)
            hid[i] += ((v[i] - mu) * inv * gam[i * 32 + lane] + bet[i * 32 + lane])
                      * (1.0f / 3.0f);
    }
#pragma unroll
    for (int i = 0; i < 4; i++) {
        size_t idx = (size_t)warp * ND + i * 32 + lane;
        h16 h, l;
        splitf(hid[i], h, l);
        g_hidh[idx] = h;
        g_hidl[idx] = l;
    }
}

// ---------------------------------------------------------------------------
// K9: per-edge logits + leaky relu + segment atomicMax
// ---------------------------------------------------------------------------
__global__ __launch_bounds__(256)
void amax_kernel(const float* __restrict__ feat, const int* __restrict__ emi,
                 const int* __restrict__ dst, const float* __restrict__ a1w,
                 const float* __restrict__ a2) {
    int warp = (blockIdx.x * blockDim.x + threadIdx.x) >> 5;
    int lane = threadIdx.x & 31;
    int node = emi[warp * NL + (NL - 1)];
    int d = dst[warp];
    float c[4];
#pragma unroll
    for (int i = 0; i < 4; i++) c[i] = feat[(size_t)node * ND + i * 32 + lane];
#pragma unroll
    for (int h = 0; h < NH; h++) {
        const float* w   = a1w + h * ND;
        const float* efr = g_eft + (size_t)warp * (NH * ND) + h * ND;
        const float* at2 = a2 + h * ND;
        float p = 0.0f;
#pragma unroll
        for (int i = 0; i < 4; i++)
            p += c[i] * w[i * 32 + lane] + efr[i * 32 + lane] * at2[i * 32 + lane];
#pragma unroll
        for (int off = 16; off; off >>= 1) p += __shfl_xor_sync(0xFFFFFFFFu, p, off);
        if (lane == 0) {
            float av = p > 0.0f ? p : 0.01f * p;
            g_a[warp * NH + h] = av;
            atomicMax(&g_menc[d * NH + h], encf(av));
        }
    }
}

// ---------------------------------------------------------------------------
// K10: e = exp(a - m[dst]); segment sum
// ---------------------------------------------------------------------------
__global__ void exps_kernel(const int* __restrict__ dst) {
    int i = blockIdx.x * 256 + threadIdx.x;
    int e = i >> 3, h = i & 7;
    int d = dst[e];
    float m = decf(g_menc[d * NH + h]);
    float ex = expf(g_a[i] - m);
    g_expa[i] = ex;
    atomicAdd(&g_s[d * NH + h], ex);
}

// ---------------------------------------------------------------------------
// K11: ft[dst] += eft * (e / s[dst])
// ---------------------------------------------------------------------------
__global__ void ftacc_kernel(const int* __restrict__ dst) {
    size_t i = (size_t)blockIdx.x * 256 + threadIdx.x;
    int e = (int)(i >> 10);
    int j = (int)(i & 1023);
    int h = j >> 7;
    int d = dst[e];
    float w = g_expa[e * NH + h] / g_s[d * NH + h];
    atomicAdd(&g_ft[(size_t)d * (NH * ND) + j], g_eft[i] * w);
}

// ---------------------------------------------------------------------------
// K12: out = ft[target_idx]
// ---------------------------------------------------------------------------
__global__ void outg_kernel(const int* __restrict__ tgt, float* __restrict__ out) {
    size_t i = (size_t)blockIdx.x * 256 + threadIdx.x;
    int t = (int)(i >> 10);
    int j = (int)(i & 1023);
    out[i] = g_ft[(size_t)tgt[t] * (NH * ND) + j];
}

// ---------------------------------------------------------------------------
extern "C" void kernel_launch(void* const* d_in, const int* in_sizes, int n_in,
                              void* d_out, int out_size) {
    const float* features = (const float*)d_in[0];
    const int*   emi      = (const int*)d_in[1];
    const int*   dst      = (const int*)d_in[2];
    const int*   tgt      = (const int*)d_in[3];
    const float* in_w     = (const float*)d_in[4];
    const float* in_b     = (const float*)d_in[5];
    const float* out_w    = (const float*)d_in[6];
    const float* out_b    = (const float*)d_in[7];
    const float* ln1_g    = (const float*)d_in[8];
    const float* ln1_b    = (const float*)d_in[9];
    const float* w1       = (const float*)d_in[10];
    const float* b1       = (const float*)d_in[11];
    const float* w2       = (const float*)d_in[12];
    const float* b2       = (const float*)d_in[13];
    const float* ln2_g    = (const float*)d_in[14];
    const float* ln2_b    = (const float*)d_in[15];
    const float* rnn_w    = (const float*)d_in[16];
    const float* rnn_b    = (const float*)d_in[17];
    const float* a1w      = (const float*)d_in[18];
    const float* a2       = (const float*)d_in[19];
    float* out = (float*)d_out;

    cudaFuncSetAttribute(hgemm, cudaFuncAttributeMaxDynamicSharedMemorySize, HG_SMEM);

    // Resolve device-global addresses (query-only; capture safe)
    float *pnqkv, *pffo, *peft;
    h16 *pfh, *pfl, *pah, *pal, *px1h, *px1l, *phh, *phl, *phidh, *phidl;
    h16 *piwf, *powf, *pw1f, *pw2f, *prwf;
    cudaGetSymbolAddress((void**)&pnqkv, g_nqkv);
    cudaGetSymbolAddress((void**)&pffo,  g_ffo);
    cudaGetSymbolAddress((void**)&peft,  g_eft);
    cudaGetSymbolAddress((void**)&pfh,   g_fh);
    cudaGetSymbolAddress((void**)&pfl,   g_fl);
    cudaGetSymbolAddress((void**)&pah,   g_ah);
    cudaGetSymbolAddress((void**)&pal,   g_al);
    cudaGetSymbolAddress((void**)&px1h,  g_x1h);
    cudaGetSymbolAddress((void**)&px1l,  g_x1l);
    cudaGetSymbolAddress((void**)&phh,   g_hh);
    cudaGetSymbolAddress((void**)&phl,   g_hl);
    cudaGetSymbolAddress((void**)&phidh, g_hidh);
    cudaGetSymbolAddress((void**)&phidl, g_hidl);
    cudaGetSymbolAddress((void**)&piwf,  g_iwf);
    cudaGetSymbolAddress((void**)&powf,  g_owf);
    cudaGetSymbolAddress((void**)&pw1f,  g_w1f);
    cudaGetSymbolAddress((void**)&pw2f,  g_w2f);
    cudaGetSymbolAddress((void**)&prwf,  g_rwf);

    // L0: convert weights to fp16 + split padded feature planes (one launch)
    wsplit_all<<<(WN5 + 255) / 256, 256>>>(in_w, out_w, w1, w2, rnn_w, features);

    // L1: zero accumulators
    zero_kernel<<<(NN * NH * ND + 255) / 256, 256>>>();

    // L2: node-level QKV = features @ in_w^T + in_b : [20096,128]x[384,128]
    hgemm<<<dim3(NNP / 128, 3), 256, HG_SMEM>>>(
        pfh, pfl, ND, piwf, ND, in_b, pnqkv, nullptr, nullptr, 384, ND, 0);

    // L3: attention (gathers node qkv via emi; node table is L2-resident)
    attn_kernel<<<NE / 8, 256>>>(emi);

    // L4: out projection -> g_ffo fp32
    hgemm<<<dim3(NELT / 128, 1), 256, HG_SMEM>>>(
        pah, pal, ND, powf, ND, out_b, pffo, nullptr, nullptr, ND, ND, 0);

    // L5: x1 = LN1(features[emi] + oproj)
    addln_kernel<<<NELT / 8, 256>>>(features, emi, ln1_g, ln1_b);

    // L6: FFN in 4 hidden N-chunks of FFC=512; FFN2 accumulates into g_ffo
    for (int c = 0; c < NFF / FFC; c++) {
        hgemm<<<dim3(NELT / 128, FFC / 128), 256, HG_SMEM>>>(
            px1h, px1l, ND,
            pw1f + (size_t)c * FFC * ND, ND,
            b1 + c * FFC, nullptr, phh, phl, FFC, ND, 1);
        hgemm<<<dim3(NELT / 128, 1), 256, HG_SMEM>>>(
            phh, phl, FFC,
            pw2f + (size_t)c * FFC, NFF,
            b2, pffo, nullptr, nullptr, ND, FFC, c == 0 ? 0 : 2);
    }

    // L7: x2 = LN2(x1 + ff); hidden = mean_L(x2) -> planes
    ln2hidden_kernel<<<NE / 8, 256>>>(ln2_g, ln2_b);

    // L8: eft = hidden @ rnn_w^T + rnn_b : [65536,128]x[1024,128]
    hgemm<<<dim3(NE / 128, (NH * ND) / 128), 256, HG_SMEM>>>(
        phidh, phidl, ND, prwf, ND, rnn_b, peft, nullptr, nullptr,
        NH * ND, ND, 0);

    // L9-12: segment softmax aggregation + output gather
    amax_kernel<<<NE / 8, 256>>>(features, emi, dst, a1w, a2);
    exps_kernel<<<NE * NH / 256, 256>>>(dst);
    ftacc_kernel<<<(int)((size_t)NE * NH * ND / 256), 256>>>(dst);
    outg_kernel<<<(int)((size_t)NT * NH * ND / 256), 256>>>(tgt, out);
}

// round 17
// speedup vs baseline: 1.8619x; 1.5847x over previous
#include <cuda_runtime.h>
#include <cuda_bf16.h>
#include <cuda_fp16.h>
#include <cstdint>
#include <math.h>

// Problem constants
#define NE    65536      // edges
#define NL    3          // metapath length
#define NELT  196608     // NE*NL tokens
#define NN    20000      // nodes
#define NNP   20096      // nodes padded to multiple of 128 (157*128)
#define NT    16384      // targets
#define ND    128        // model dim
#define NFF   2048       // FF dim
#define NAH   4          // attention heads
#define NH    8          // output heads
#define FFC   512        // FFN hidden N-chunk width (NFF/4)

typedef __half h16;

// ---------------------------------------------------------------------------
// Static device scratch (~1.0 GB; must stay < 2 GB or host link fails with
// GOTPCREL relocation overflow — learned in R4)
// ---------------------------------------------------------------------------
__device__ h16   g_fh    [(size_t)NNP * ND];         // feature split planes (A)
__device__ h16   g_fl    [(size_t)NNP * ND];
__device__ float g_nqkv  [(size_t)NNP * 3 * ND];     // per-NODE qkv projection
__device__ h16   g_ah    [(size_t)NELT * ND];        // attention out planes
__device__ h16   g_al    [(size_t)NELT * ND];
__device__ h16   g_x1h   [(size_t)NELT * ND];        // post-LN1 split planes
__device__ h16   g_x1l   [(size_t)NELT * ND];        // (lo kept for LN2 residual)
__device__ h16   g_hh    [(size_t)NELT * FFC];       // FFN hidden (fp16, single plane)
__device__ float g_ffo   [(size_t)NELT * ND];        // outproj out, then FFN out
__device__ h16   g_hidh  [(size_t)NE * ND];          // hidden (mean over L)
__device__ h16   g_hidl  [(size_t)NE * ND];
__device__ float g_eft   [(size_t)NE * NH * ND];     // rnn projection fp32
__device__ float g_a     [(size_t)NE * NH];
__device__ float g_expa  [(size_t)NE * NH];
__device__ unsigned g_menc[(size_t)NN * NH];
__device__ float g_s     [(size_t)NN * NH];
__device__ float g_ft    [(size_t)NN * NH * ND];
// weight planes (single fp16 plane each — W residual is a dropped term)
__device__ h16 g_iwf[3 * ND * ND];
__device__ h16 g_owf[ND * ND];
__device__ h16 g_w1f[NFF * ND];
__device__ h16 g_w2f[ND * NFF];
__device__ h16 g_rwf[NH * ND * ND];

// ---------------------------------------------------------------------------
// Helpers
// ---------------------------------------------------------------------------
__device__ __forceinline__ uint32_t smem_u32(const void* p) {
    uint32_t a;
    asm("{ .reg .u64 t; cvta.to.shared.u64 t, %1; cvt.u32.u64 %0, t; }" : "=r"(a) : "l"(p));
    return a;
}
__device__ __forceinline__ void ldsm4(uint32_t* r, uint32_t addr) {
    asm volatile("ldmatrix.sync.aligned.m8n8.x4.shared.b16 {%0,%1,%2,%3}, [%4];"
                 : "=r"(r[0]), "=r"(r[1]), "=r"(r[2]), "=r"(r[3]) : "r"(addr));
}
__device__ __forceinline__ void mma16816(float* c, const uint32_t* a,
                                         uint32_t b0, uint32_t b1) {
    asm volatile("mma.sync.aligned.m16n8k16.row.col.f32.f16.f16.f32 "
                 "{%0,%1,%2,%3}, {%4,%5,%6,%7}, {%8,%9}, {%0,%1,%2,%3};"
                 : "+f"(c[0]), "+f"(c[1]), "+f"(c[2]), "+f"(c[3])
                 : "r"(a[0]), "r"(a[1]), "r"(a[2]), "r"(a[3]), "r"(b0), "r"(b1));
}
__device__ __forceinline__ void cpa16(uint32_t saddr, const void* g) {
    asm volatile("cp.async.cg.shared.global [%0], [%1], 16;" :: "r"(saddr), "l"(g));
}
#define CPA_COMMIT() asm volatile("cp.async.commit_group;" ::: "memory")
#define CPA_WAIT1()  asm volatile("cp.async.wait_group 1;" ::: "memory")

__device__ __forceinline__ void splitf(float v, h16& h, h16& l) {
    h = __float2half(v);
    l = __float2half(v - __half2float(h));
}
__device__ __forceinline__ unsigned encf(float f) {
    unsigned u = __float_as_uint(f);
    return (u & 0x80000000u) ? ~u : (u | 0x80000000u);
}
__device__ __forceinline__ float decf(unsigned u) {
    return (u & 0x80000000u) ? __uint_as_float(u ^ 0x80000000u)
                             : __uint_as_float(~u);
}

// ---------------------------------------------------------------------------
// HMMA split-fp16 GEMM, 3-stage cp.async ring (R11/R16 measured-optimal shape).
// PASSES=2: C = (Ahi+Alo) @ Wf^T   PASSES=1: C = Ahi @ Wf^T (Alo ignored,
// its plane loads / ldsm / MMAs compiled away).
// 256 threads, 8 warps (4m x 2n, warp tile 32x64), CTA tile 128x128,
// K chunks of 32. Stage = planes {Ah, [Al], Wf} of 128x32 fp16.
// mode 0: Cf = acc + bias.  mode 1: relu(acc+bias) -> split fp16 (Chi+Clo).
// mode 2: Cf += acc.        mode 3: relu(acc+bias) -> fp16 Chi only.
// All dims are exact multiples of tiles -> no bounds checks.
// ---------------------------------------------------------------------------
#define SP 40                                   // padded SMEM row stride (elems)
#define PLS  (128 * SP * 2)                     // plane stride bytes (10240)
#define STG3 (3 * PLS)                          // stage stride bytes (30720)
#define NSTG 3                                  // ring depth
#define HG_SMEM (NSTG * STG3)                   // 92160 bytes dynamic SMEM

template<int PASSES>
__global__ __launch_bounds__(256)
void hgemm(const h16* __restrict__ Ahi, const h16* __restrict__ Alo, int lda,
           const h16* __restrict__ Wf, int ldw,
           const float* __restrict__ bias,
           float* __restrict__ Cf, h16* __restrict__ Chi, h16* __restrict__ Clo,
           int ldc, int K, int mode) {
    extern __shared__ h16 smdyn[];
    const uint32_t sbase = smem_u32(smdyn);

    const int tid  = threadIdx.x;
    const int wid  = tid >> 5;
    const int lane = tid & 31;
    const int wm   = wid & 3;         // 4 m-groups * 32 rows
    const int wn   = wid >> 2;        // 2 n-groups * 64 cols
    const size_t bm = (size_t)blockIdx.x * 128;
    const size_t bn = (size_t)blockIdx.y * 128;

    // staging table: unit u = tid + 256*i; i in {0,1}=Ah, {2,3}=Al, {4,5}=Wf
    const h16* gp[6];
    uint32_t doff[6];
#pragma unroll
    for (int i = 0; i < 6; i++) {
        int u = tid + 256 * i;
        int plane = u >> 9;           // 0=Ah 1=Al 2=Wf
        int rem = u & 511;
        int row = rem >> 2;
        int q = rem & 3;
        const h16* b;
        int ld;
        if (plane == 0)      { b = Ahi + bm * (size_t)lda; ld = lda; }
        else if (plane == 1) { b = Alo + bm * (size_t)lda; ld = lda; }
        else                 { b = Wf  + bn * (size_t)ldw; ld = ldw; }
        gp[i] = b + (size_t)row * ld + q * 8;
        doff[i] = plane * PLS + (row * SP + q * 8) * 2;
    }
#define ISSUE(k0, slot) do {                                                 \
        uint32_t sb_ = sbase + (slot) * STG3;                                \
        _Pragma("unroll")                                                    \
        for (int i = 0; i < 6; i++)                                          \
            if (PASSES == 2 || (i >> 1) != 1)                                \
                cpa16(sb_ + doff[i], gp[i] + (k0));                          \
    } while (0)

    // ldmatrix coords
    const int frow = lane & 15;
    const int fcol = (lane >> 4) << 3;

    float acc[2][8][4];
#pragma unroll
    for (int i = 0; i < 2; i++)
#pragma unroll
        for (int j = 0; j < 8; j++)
#pragma unroll
            for (int q = 0; q < 4; q++) acc[i][j][q] = 0.0f;

    const int nch = K >> 5;

    // prologue: chunks 0 and 1 into slots 0, 1
    ISSUE(0, 0);  CPA_COMMIT();
    ISSUE(32, 1); CPA_COMMIT();

    int put = 2;                      // next ring slot the loader writes
    int get = 0;                      // ring slot the consumer reads
    for (int c = 0; c < nch; c++) {
        CPA_WAIT1();                  // chunk c's group retired (FIFO)
        __syncthreads();
        if (c + 2 < nch) {
            ISSUE((c + 2) << 5, put);
            if (++put == NSTG) put = 0;
        }
        CPA_COMMIT();                 // empty-commit keeps the FIFO geometry
        const uint32_t cb = sbase + get * STG3;
        if (++get == NSTG) get = 0;
#pragma unroll
        for (int kk = 0; kk < 32; kk += 16) {
            uint32_t ah[2][4], al[2][4];
#pragma unroll
            for (int mf = 0; mf < 2; mf++) {
                uint32_t ra = ((wm * 32 + mf * 16 + frow) * SP + kk + fcol) * 2;
                ldsm4(ah[mf], cb + ra);
                if (PASSES == 2) ldsm4(al[mf], cb + PLS + ra);
            }
#pragma unroll
            for (int g = 0; g < 4; g++) {
                uint32_t b[4];
                ldsm4(b, cb + 2 * PLS +
                      ((wn * 64 + g * 16 + frow) * SP + kk + fcol) * 2);
#pragma unroll
                for (int mf = 0; mf < 2; mf++) {
                    mma16816(acc[mf][g * 2],     ah[mf], b[0], b[2]);
                    mma16816(acc[mf][g * 2 + 1], ah[mf], b[1], b[3]);
                    if (PASSES == 2) {
                        mma16816(acc[mf][g * 2],     al[mf], b[0], b[2]);
                        mma16816(acc[mf][g * 2 + 1], al[mf], b[1], b[3]);
                    }
                }
            }
        }
    }

    // Epilogue. D thread map: row = t/4 (+8 for regs 2,3), col = 2*(t%4)+{0,1}
    const int tr = lane >> 2;
    const int tc = (lane & 3) * 2;
    const size_t m0 = bm + wm * 32;
    const size_t n0 = bn + wn * 64;
#pragma unroll
    for (int mf = 0; mf < 2; mf++) {
#pragma unroll
        for (int hh = 0; hh < 2; hh++) {
            size_t row = m0 + mf * 16 + tr + hh * 8;
#pragma unroll
            for (int nf = 0; nf < 8; nf++) {
                size_t col = n0 + nf * 8 + tc;
                float a0 = acc[mf][nf][hh * 2];
                float a1 = acc[mf][nf][hh * 2 + 1];
                if (mode == 0) {
                    float2 o;
                    o.x = a0 + bias[col];
                    o.y = a1 + bias[col + 1];
                    *(float2*)&Cf[row * (size_t)ldc + col] = o;
                } else if (mode == 2) {
                    float2 old = *(float2*)&Cf[row * (size_t)ldc + col];
                    old.x += a0;
                    old.y += a1;
                    *(float2*)&Cf[row * (size_t)ldc + col] = old;
                } else if (mode == 3) {
                    float v0 = fmaxf(a0 + bias[col], 0.0f);
                    float v1 = fmaxf(a1 + bias[col + 1], 0.0f);
                    __half2 hp;
                    hp.x = __float2half(v0);
                    hp.y = __float2half(v1);
                    *(__half2*)&Chi[row * (size_t)ldc + col] = hp;
                } else {
                    float v0 = fmaxf(a0 + bias[col], 0.0f);
                    float v1 = fmaxf(a1 + bias[col + 1], 0.0f);
                    h16 h0, l0, h1, l1;
                    splitf(v0, h0, l0);
                    splitf(v1, h1, l1);
                    __half2 hp; hp.x = h0; hp.y = h1;
                    __half2 lp; lp.x = l0; lp.y = l1;
                    *(__half2*)&Chi[row * (size_t)ldc + col] = hp;
                    *(__half2*)&Clo[row * (size_t)ldc + col] = lp;
                }
            }
        }
    }
#undef ISSUE
}

// ---------------------------------------------------------------------------
// Fused weight-convert + feature-split (one launch)
// ---------------------------------------------------------------------------
#define WN0 (3 * ND * ND)
#define WN1 (WN0 + ND * ND)
#define WN2 (WN1 + NFF * ND)
#define WN3 (WN2 + ND * NFF)
#define WN4 (WN3 + NH * ND * ND)
#define WN5 (WN4 + NNP * ND)

__global__ void wsplit_all(const float* __restrict__ in_w,
                           const float* __restrict__ out_w,
                           const float* __restrict__ w1,
                           const float* __restrict__ w2,
                           const float* __restrict__ rnn_w,
                           const float* __restrict__ feat) {
    int i = blockIdx.x * 256 + threadIdx.x;
    if (i >= WN5) return;
    if (i >= WN4) {
        int j = i - WN4;              // padded feature planes (A operand: split)
        float v = (j < NN * ND) ? feat[j] : 0.0f;
        h16 hh, ll;
        splitf(v, hh, ll);
        g_fh[j] = hh;
        g_fl[j] = ll;
        return;
    }
    const float* s; h16* h; int j;
    if (i < WN0)      { s = in_w;  h = g_iwf; j = i; }
    else if (i < WN1) { s = out_w; h = g_owf; j = i - WN0; }
    else if (i < WN2) { s = w1;    h = g_w1f; j = i - WN1; }
    else if (i < WN3) { s = w2;    h = g_w2f; j = i - WN2; }
    else              { s = rnn_w; h = g_rwf; j = i - WN3; }
    h[j] = __float2half(s[j]);
}

// ---------------------------------------------------------------------------
// K0: zero per-launch accumulators (float4 over g_ft)
// ---------------------------------------------------------------------------
__global__ void zero_kernel() {
    int i = blockIdx.x * 256 + threadIdx.x;   // NN*NH*ND/4 threads exactly
    float4 z = make_float4(0.f, 0.f, 0.f, 0.f);
    *(float4*)&g_ft[(size_t)i * 4] = z;
    if (i < NN * NH) { g_s[i] = 0.0f; g_menc[i] = 0u; }
}

// ---------------------------------------------------------------------------
// K3: tiny attention (L=3, AH=4, HD=32) — one warp per edge, vectorized
// (measured 36us). Node qkv table is L2-resident.
// ---------------------------------------------------------------------------
__global__ __launch_bounds__(256)
void attn_kernel(const int* __restrict__ emi) {
    int warp = (blockIdx.x * blockDim.x + threadIdx.x) >> 5;
    int lane = threadIdx.x & 31;

    float4 q[NL], k[NL], v[NL];
#pragma unroll
    for (int l = 0; l < NL; l++) {
        int node = emi[warp * NL + l];
        const float* base = g_nqkv + (size_t)node * 384 + lane * 4;
        q[l] = *(const float4*)(base);
        k[l] = *(const float4*)(base + 128);
        v[l] = *(const float4*)(base + 256);
    }

    const float scale = 0.1767766952966369f; // 1/sqrt(32)
    float s[NL][NL];
#pragma unroll
    for (int l = 0; l < NL; l++)
#pragma unroll
        for (int m = 0; m < NL; m++) {
            float p = q[l].x * k[m].x + q[l].y * k[m].y
                    + q[l].z * k[m].z + q[l].w * k[m].w;
            p += __shfl_xor_sync(0xFFFFFFFFu, p, 1);
            p += __shfl_xor_sync(0xFFFFFFFFu, p, 2);
            p += __shfl_xor_sync(0xFFFFFFFFu, p, 4);
            s[l][m] = p * scale;
        }

#pragma unroll
    for (int l = 0; l < NL; l++) {
        float mx = fmaxf(s[l][0], fmaxf(s[l][1], s[l][2]));
        float e0 = expf(s[l][0] - mx);
        float e1 = expf(s[l][1] - mx);
        float e2 = expf(s[l][2] - mx);
        float inv = 1.0f / (e0 + e1 + e2);
        float o0 = (e0 * v[0].x + e1 * v[1].x + e2 * v[2].x) * inv;
        float o1 = (e0 * v[0].y + e1 * v[1].y + e2 * v[2].y) * inv;
        float o2 = (e0 * v[0].z + e1 * v[1].z + e2 * v[2].z) * inv;
        float o3 = (e0 * v[0].w + e1 * v[1].w + e2 * v[2].w) * inv;
        size_t idx = ((size_t)warp * NL + l) * ND + lane * 4;
        h16 h0, l0, h1, l1, h2, l2, h3, l3;
        splitf(o0, h0, l0); splitf(o1, h1, l1);
        splitf(o2, h2, l2); splitf(o3, h3, l3);
        __half2 hp0, hp1, lp0, lp1;
        hp0.x = h0; hp0.y = h1; hp1.x = h2; hp1.y = h3;
        lp0.x = l0; lp0.y = l1; lp1.x = l2; lp1.y = l3;
        uint2 hv, lv;
        hv.x = *(uint32_t*)&hp0; hv.y = *(uint32_t*)&hp1;
        lv.x = *(uint32_t*)&lp0; lv.y = *(uint32_t*)&lp1;
        *(uint2*)&g_ah[idx] = hv;
        *(uint2*)&g_al[idx] = lv;
    }
}

// ---------------------------------------------------------------------------
// K5: x1 = LN1(features[emi] + oproj); writes split planes
// ---------------------------------------------------------------------------
__global__ __launch_bounds__(256)
void addln_kernel(const float* __restrict__ feat, const int* __restrict__ emi,
                  const float* __restrict__ gam, const float* __restrict__ bet) {
    int warp = (blockIdx.x * blockDim.x + threadIdx.x) >> 5;   // token index
    int lane = threadIdx.x & 31;
    int node = emi[warp];
    const float* xr = feat + (size_t)node * ND;
    const float* yr = g_ffo + (size_t)warp * ND;
    float v[4], s = 0.0f;
#pragma unroll
    for (int i = 0; i < 4; i++) {
        v[i] = xr[i * 32 + lane] + yr[i * 32 + lane];
        s += v[i];
    }
#pragma unroll
    for (int off = 16; off; off >>= 1) s += __shfl_xor_sync(0xFFFFFFFFu, s, off);
    float mu = s * (1.0f / 128.0f);
    float vs = 0.0f;
#pragma unroll
    for (int i = 0; i < 4; i++) { float d = v[i] - mu; vs += d * d; }
#pragma unroll
    for (int off = 16; off; off >>= 1) vs += __shfl_xor_sync(0xFFFFFFFFu, vs, off);
    float inv = rsqrtf(vs * (1.0f / 128.0f) + 1e-5f);
#pragma unroll
    for (int i = 0; i < 4; i++) {
        size_t idx = (size_t)warp * ND + i * 32 + lane;
        float r = (v[i] - mu) * inv * gam[i * 32 + lane] + bet[i * 32 + lane];
        h16 h, l;
        splitf(r, h, l);
        g_x1h[idx] = h;
        g_x1l[idx] = l;
    }
}

// ---------------------------------------------------------------------------
// K7: LN2 + mean over L -> hidden planes (x1 reconstructed from planes)
// ---------------------------------------------------------------------------
__global__ __launch_bounds__(256)
void ln2hidden_kernel(const float* __restrict__ gam, const float* __restrict__ bet) {
    int warp = (blockIdx.x * blockDim.x + threadIdx.x) >> 5;
    int lane = threadIdx.x & 31;
    float hid[4] = {0, 0, 0, 0};
#pragma unroll
    for (int l = 0; l < NL; l++) {
        size_t r = (size_t)warp * NL + l;
        const float* yr = g_ffo + r * ND;
        float v[4], s = 0.0f;
#pragma unroll
        for (int i = 0; i < 4; i++) {
            size_t idx = r * ND + i * 32 + lane;
            float x1 = __half2float(g_x1h[idx]) + __half2float(g_x1l[idx]);
            v[i] = x1 + yr[i * 32 + lane];
            s += v[i];
        }
#pragma unroll
        for (int off = 16; off; off >>= 1) s += __shfl_xor_sync(0xFFFFFFFFu, s, off);
        float mu = s * (1.0f / 128.0f);
        float vs = 0.0f;
#pragma unroll
        for (int i = 0; i < 4; i++) { float d = v[i] - mu; vs += d * d; }
#pragma unroll
        for (int off = 16; off; off >>= 1) vs += __shfl_xor_sync(0xFFFFFFFFu, vs, off);
        float inv = rsqrtf(vs * (1.0f / 128.0f) + 1e-5f);
#pragma unroll
        for (int i = 0; i < 4; i++)
            hid[i] += ((v[i] - mu) * inv * gam[i * 32 + lane] + bet[i * 32 + lane])
                      * (1.0f / 3.0f);
    }
#pragma unroll
    for (int i = 0; i < 4; i++) {
        size_t idx = (size_t)warp * ND + i * 32 + lane;
        h16 h, l;
        splitf(hid[i], h, l);
        g_hidh[idx] = h;
        g_hidl[idx] = l;
    }
}

// ---------------------------------------------------------------------------
// K9: per-edge logits + leaky relu + segment atomicMax
// ---------------------------------------------------------------------------
__global__ __launch_bounds__(256)
void amax_kernel(const float* __restrict__ feat, const int* __restrict__ emi,
                 const int* __restrict__ dst, const float* __restrict__ a1w,
                 const float* __restrict__ a2) {
    int warp = (blockIdx.x * blockDim.x + threadIdx.x) >> 5;
    int lane = threadIdx.x & 31;
    int node = emi[warp * NL + (NL - 1)];
    int d = dst[warp];
    float c[4];
#pragma unroll
    for (int i = 0; i < 4; i++) c[i] = feat[(size_t)node * ND + i * 32 + lane];
#pragma unroll
    for (int h = 0; h < NH; h++) {
        const float* w   = a1w + h * ND;
        const float* efr = g_eft + (size_t)warp * (NH * ND) + h * ND;
        const float* at2 = a2 + h * ND;
        float p = 0.0f;
#pragma unroll
        for (int i = 0; i < 4; i++)
            p += c[i] * w[i * 32 + lane] + efr[i * 32 + lane] * at2[i * 32 + lane];
#pragma unroll
        for (int off = 16; off; off >>= 1) p += __shfl_xor_sync(0xFFFFFFFFu, p, off);
        if (lane == 0) {
            float av = p > 0.0f ? p : 0.01f * p;
            g_a[warp * NH + h] = av;
            atomicMax(&g_menc[d * NH + h], encf(av));
        }
    }
}

// ---------------------------------------------------------------------------
// K10: e = exp(a - m[dst]); segment sum
// ---------------------------------------------------------------------------
__global__ void exps_kernel(const int* __restrict__ dst) {
    int i = blockIdx.x * 256 + threadIdx.x;
    int e = i >> 3, h = i & 7;
    int d = dst[e];
    float m = decf(g_menc[d * NH + h]);
    float ex = expf(g_a[i] - m);
    g_expa[i] = ex;
    atomicAdd(&g_s[d * NH + h], ex);
}

// ---------------------------------------------------------------------------
// K11: ft[dst] += eft * (e / s[dst]) — 4 elems/thread, vector red (sm_90+)
// ---------------------------------------------------------------------------
__global__ void ftacc_kernel(const int* __restrict__ dst) {
    size_t i4 = (size_t)blockIdx.x * 256 + threadIdx.x;   // NE*NH*ND/4 threads
    size_t base = i4 * 4;
    int e = (int)(base >> 10);
    int j = (int)(base & 1023);
    int h = j >> 7;
    int d = dst[e];
    float w = g_expa[e * NH + h] / g_s[d * NH + h];
    float4 v = *(const float4*)&g_eft[base];
    float* p = &g_ft[(size_t)d * (NH * ND) + j];
    asm volatile("red.global.add.v4.f32 [%0], {%1, %2, %3, %4};"
                 :: "l"(p), "f"(v.x * w), "f"(v.y * w), "f"(v.z * w), "f"(v.w * w)
                 : "memory");
}

// ---------------------------------------------------------------------------
// K12: out = ft[target_idx] — float4
// ---------------------------------------------------------------------------
__global__ void outg_kernel(const int* __restrict__ tgt, float* __restrict__ out) {
    size_t i4 = (size_t)blockIdx.x * 256 + threadIdx.x;   // NT*NH*ND/4 threads
    size_t base = i4 * 4;
    int t = (int)(base >> 10);
    int j = (int)(base & 1023);
    *(float4*)&out[base] = *(const float4*)&g_ft[(size_t)tgt[t] * (NH * ND) + j];
}

// ---------------------------------------------------------------------------
extern "C" void kernel_launch(void* const* d_in, const int* in_sizes, int n_in,
                              void* d_out, int out_size) {
    const float* features = (const float*)d_in[0];
    const int*   emi      = (const int*)d_in[1];
    const int*   dst      = (const int*)d_in[2];
    const int*   tgt      = (const int*)d_in[3];
    const float* in_w     = (const float*)d_in[4];
    const float* in_b     = (const float*)d_in[5];
    const float* out_w    = (const float*)d_in[6];
    const float* out_b    = (const float*)d_in[7];
    const float* ln1_g    = (const float*)d_in[8];
    const float* ln1_b    = (const float*)d_in[9];
    const float* w1       = (const float*)d_in[10];
    const float* b1       = (const float*)d_in[11];
    const float* w2       = (const float*)d_in[12];
    const float* b2       = (const float*)d_in[13];
    const float* ln2_g    = (const float*)d_in[14];
    const float* ln2_b    = (const float*)d_in[15];
    const float* rnn_w    = (const float*)d_in[16];
    const float* rnn_b    = (const float*)d_in[17];
    const float* a1w      = (const float*)d_in[18];
    const float* a2       = (const float*)d_in[19];
    float* out = (float*)d_out;

    cudaFuncSetAttribute(hgemm<2>, cudaFuncAttributeMaxDynamicSharedMemorySize, HG_SMEM);
    cudaFuncSetAttribute(hgemm<1>, cudaFuncAttributeMaxDynamicSharedMemorySize, HG_SMEM);

    // Resolve device-global addresses (query-only; capture safe)
    float *pnqkv, *pffo, *peft;
    h16 *pfh, *pfl, *pah, *pal, *px1h, *phh, *phidh, *phidl;
    h16 *piwf, *powf, *pw1f, *pw2f, *prwf;
    cudaGetSymbolAddress((void**)&pnqkv, g_nqkv);
    cudaGetSymbolAddress((void**)&pffo,  g_ffo);
    cudaGetSymbolAddress((void**)&peft,  g_eft);
    cudaGetSymbolAddress((void**)&pfh,   g_fh);
    cudaGetSymbolAddress((void**)&pfl,   g_fl);
    cudaGetSymbolAddress((void**)&pah,   g_ah);
    cudaGetSymbolAddress((void**)&pal,   g_al);
    cudaGetSymbolAddress((void**)&px1h,  g_x1h);
    cudaGetSymbolAddress((void**)&phh,   g_hh);
    cudaGetSymbolAddress((void**)&phidh, g_hidh);
    cudaGetSymbolAddress((void**)&phidl, g_hidl);
    cudaGetSymbolAddress((void**)&piwf,  g_iwf);
    cudaGetSymbolAddress((void**)&powf,  g_owf);
    cudaGetSymbolAddress((void**)&pw1f,  g_w1f);
    cudaGetSymbolAddress((void**)&pw2f,  g_w2f);
    cudaGetSymbolAddress((void**)&prwf,  g_rwf);

    // L0: convert weights to fp16 + split padded feature planes (one launch)
    wsplit_all<<<(WN5 + 255) / 256, 256>>>(in_w, out_w, w1, w2, rnn_w, features);

    // L1: zero accumulators (float4 over g_ft; NN*NH*ND/4 threads exactly)
    zero_kernel<<<NN * NH * ND / 4 / 256, 256>>>();

    // L2: node-level QKV = features @ in_w^T + in_b : [20096,128]x[384,128]
    hgemm<2><<<dim3(NNP / 128, 3), 256, HG_SMEM>>>(
        pfh, pfl, ND, piwf, ND, in_b, pnqkv, nullptr, nullptr, 384, ND, 0);

    // L3: attention (gathers node qkv via emi; node table is L2-resident)
    attn_kernel<<<NE / 8, 256>>>(emi);

    // L4: out projection -> g_ffo fp32 (2-pass: attention output split planes)
    hgemm<2><<<dim3(NELT / 128, 1), 256, HG_SMEM>>>(
        pah, pal, ND, powf, ND, out_b, pffo, nullptr, nullptr, ND, ND, 0);

    // L5: x1 = LN1(features[emi] + oproj)
    addln_kernel<<<NELT / 8, 256>>>(features, emi, ln1_g, ln1_b);

    // L6: FFN in 4 hidden N-chunks; SINGLE-PASS fp16 A (error budget allows:
    // adds ~2e-4 per FFN GEMM; total stays ~3.5e-4 < 1e-3)
    for (int c = 0; c < NFF / FFC; c++) {
        // FFN1 chunk: h = relu(x1 @ w1^T + b1) -> fp16 (mode 3, hi only)
        hgemm<1><<<dim3(NELT / 128, FFC / 128), 256, HG_SMEM>>>(
            px1h, px1h, ND,
            pw1f + (size_t)c * FFC * ND, ND,
            b1 + c * FFC, nullptr, phh, nullptr, FFC, ND, 3);
        // FFN2 chunk: ffo (+)= h @ w2^T (+ b2 on first chunk)
        hgemm<1><<<dim3(NELT / 128, 1), 256, HG_SMEM>>>(
            phh, phh, FFC,
            pw2f + (size_t)c * FFC, NFF,
            b2, pffo, nullptr, nullptr, ND, FFC, c == 0 ? 0 : 2);
    }

    // L7: x2 = LN2(x1 + ff); hidden = mean_L(x2) -> planes
    ln2hidden_kernel<<<NE / 8, 256>>>(ln2_g, ln2_b);

    // L8: eft = hidden @ rnn_w^T + rnn_b (2-pass; feeds the softmax logits)
    hgemm<2><<<dim3(NE / 128, (NH * ND) / 128), 256, HG_SMEM>>>(
        phidh, phidl, ND, prwf, ND, rnn_b, peft, nullptr, nullptr,
        NH * ND, ND, 0);

    // L9-12: segment softmax aggregation + output gather
    amax_kernel<<<NE / 8, 256>>>(features, emi, dst, a1w, a2);
    exps_kernel<<<NE * NH / 256, 256>>>(dst);
    ftacc_kernel<<<(int)((size_t)NE * NH * ND / 4 / 256), 256>>>(dst);
    outg_kernel<<<(int)((size_t)NT * NH * ND / 4 / 256), 256>>>(tgt, out);
}